// round 6
// baseline (speedup 1.0000x reference)
#include <cuda_runtime.h>
#include <cstdint>

// LambdaLoss: B=4096 lists, L=128 items.
// loss = mean over valid lists of
//        [ sum_{i,j: rel_i>rel_j} (rel_i-rel_j)*softplus(-(p_i-p_j)) / cnt ]
//
// Factorized: softplus(-(p_w-p_l)) = ln(1 + e^{p_l}*e^{-p_w}); precompute
// e_i = exp(p_i), rec_i = exp(-p_i) -> one lg2 per pair, no per-pair exp.
// Counting-sort by rel: winner = higher sorted index, so orientation is
// index-derived (3 of 5 pair kinds fully branch-free; v2 pairs share one
// index-only predicate). Within-class pairs have rd==0 -> contribute 0.
// 2x2 ring tiling: 64 threads/list, thread lj owns sorted items lj, lj+64;
// k=1..31 -> 4 pairs/iter (2 LDS.128), k=32 -> 2, plus {lj,lj+64}. 127/thread.
// R6: group-of-2 k iterations (load MLP + 8 independent lg2 chains/group),
// dup region written at scatter (one less barrier + copy pass).

#define LL_B   4096
#define LL_L   128
#define LOG2E  1.4426950408889634f
#define LN2    0.6931471805599453f

__device__ float g_sum   = 0.0f;
__device__ int   g_valid = 0;
__device__ int   g_done  = 0;

__device__ __forceinline__ float fast_ex2(float x) {
    float r; asm("ex2.approx.f32 %0, %1;" : "=f"(r) : "f"(x)); return r;
}
__device__ __forceinline__ float fast_lg2(float x) {
    float r; asm("lg2.approx.f32 %0, %1;" : "=f"(r) : "f"(x)); return r;
}

__global__ __launch_bounds__(128) void ll_main_kernel(
    const float* __restrict__ pred,
    const float* __restrict__ rel,
    float* __restrict__ out)
{
    __shared__ float4 S[2][160];     // sorted (e, rec, rel, _); [128,160) dup
    __shared__ int    hist[2][8];
    __shared__ int    base[2][8];
    __shared__ float  wsum[4];

    const int t    = threadIdx.x;
    const int half = t >> 6;
    const int lj   = t & 63;
    const int list = blockIdx.x * 2 + half;

    const float* P = pred + list * LL_L;
    const float* R = rel  + list * LL_L;

    const float p0 = P[lj], p1 = P[lj + 64];
    const float r0 = R[lj], r1 = R[lj + 64];
    const int   c0 = (int)r0, c1 = (int)r1;   // rel in {0..4}

    // exp work is independent of the sort — issue it before the barriers
    const float q0 = p0 * LOG2E, q1 = p1 * LOG2E;
    const float e0 = fast_ex2(q0), rc0 = fast_ex2(-q0);
    const float e1 = fast_ex2(q1), rc1 = fast_ex2(-q1);

    if (lj < 8) hist[half][lj] = 0;
    __syncthreads();
    atomicAdd(&hist[half][c0], 1);
    atomicAdd(&hist[half][c1], 1);
    __syncthreads();
    if (lj == 0) {
        int a = 0;
#pragma unroll
        for (int c = 0; c < 5; c++) { base[half][c] = a; a += hist[half][c]; }
    }
    __syncthreads();

    // rank + scatter; writers to [0,32) also write the ring-wrap duplicate
    const int pos0 = atomicAdd(&base[half][c0], 1);
    const int pos1 = atomicAdd(&base[half][c1], 1);
    const float4 t0 = make_float4(e0, rc0, r0, 0.0f);
    const float4 t1 = make_float4(e1, rc1, r1, 0.0f);
    S[half][pos0] = t0;
    S[half][pos1] = t1;
    if (pos0 < 32) S[half][pos0 + 128] = t0;
    if (pos1 < 32) S[half][pos1 + 128] = t1;
    __syncthreads();

    const float4* Sp = S[half];
    const float4 a = Sp[lj];
    const float4 b = Sp[lj + 64];
    const float eA = a.x, recA = a.y, rA = a.z;
    const float eB = b.x, recB = b.y, rB = b.z;

    float acc0 = 0.0f, acc1 = 0.0f, acc2 = 0.0f, acc3 = 0.0f;

    // group-of-2 k iterations: 4 loads up front, 8 independent lg2 chains
#pragma unroll
    for (int kk = 1; kk < 31; kk += 2) {
        const float4 v1a = Sp[lj + kk];
        const float4 v2a = Sp[lj + 64 + kk];
        const float4 v1b = Sp[lj + kk + 1];
        const float4 v2b = Sp[lj + 64 + kk + 1];
        const bool nwa = (lj + kk)     < 64;
        const bool nwb = (lj + kk + 1) < 64;

        acc0 = fmaf(v1a.z - rA, fast_lg2(1.0f + eA * v1a.y), acc0);
        acc1 = fmaf(rB - v1a.z, fast_lg2(1.0f + v1a.x * recB), acc1);
        {
            float tt = nwa ? (eA * v2a.y) : (v2a.x * recA);
            acc2 = fmaf(fabsf(v2a.z - rA), fast_lg2(1.0f + tt), acc2);
        }
        {
            float tt = nwa ? (eB * v2a.y) : (v2a.x * recB);
            acc3 = fmaf(fabsf(v2a.z - rB), fast_lg2(1.0f + tt), acc3);
        }
        acc0 = fmaf(v1b.z - rA, fast_lg2(1.0f + eA * v1b.y), acc0);
        acc1 = fmaf(rB - v1b.z, fast_lg2(1.0f + v1b.x * recB), acc1);
        {
            float tt = nwb ? (eA * v2b.y) : (v2b.x * recA);
            acc2 = fmaf(fabsf(v2b.z - rA), fast_lg2(1.0f + tt), acc2);
        }
        {
            float tt = nwb ? (eB * v2b.y) : (v2b.x * recB);
            acc3 = fmaf(fabsf(v2b.z - rB), fast_lg2(1.0f + tt), acc3);
        }
    }
    {   // k = 31
        const float4 v1 = Sp[lj + 31];
        const float4 v2 = Sp[lj + 95];
        const bool nw = (lj + 31) < 64;
        acc0 = fmaf(v1.z - rA, fast_lg2(1.0f + eA * v1.y), acc0);
        acc1 = fmaf(rB - v1.z, fast_lg2(1.0f + v1.x * recB), acc1);
        {
            float tt = nw ? (eA * v2.y) : (v2.x * recA);
            acc2 = fmaf(fabsf(v2.z - rA), fast_lg2(1.0f + tt), acc2);
        }
        {
            float tt = nw ? (eB * v2.y) : (v2.x * recB);
            acc3 = fmaf(fabsf(v2.z - rB), fast_lg2(1.0f + tt), acc3);
        }
    }
    {   // k = 32: two distance-32 pairs only
        const float4 v1 = Sp[lj + 32];
        acc0 = fmaf(v1.z - rA, fast_lg2(1.0f + eA * v1.y), acc0);
        const float4 v2 = Sp[lj + 96];
        const bool nw = lj < 32;
        float tt = nw ? (eB * v2.y) : (v2.x * recB);
        acc1 = fmaf(fabsf(v2.z - rB), fast_lg2(1.0f + tt), acc1);
    }
    // distance-64 pair {lj, lj+64}: B is higher sorted index
    acc2 = fmaf(rB - rA, fast_lg2(1.0f + eA * recB), acc2);

    float acc = (acc0 + acc1) + (acc2 + acc3);

    // reduce within half-block (2 warps per list)
#pragma unroll
    for (int off = 16; off; off >>= 1)
        acc += __shfl_xor_sync(0xffffffffu, acc, off);
    if ((t & 31) == 0) wsum[t >> 5] = acc;
    __syncthreads();

    if (lj == 0) {
        float s = (wsum[half * 2] + wsum[half * 2 + 1]) * LN2;
        const int n0 = hist[half][0], n1 = hist[half][1], n2 = hist[half][2];
        const int n3 = hist[half][3], n4 = hist[half][4];
        const int cnt = n1 * n0
                      + n2 * (n0 + n1)
                      + n3 * (n0 + n1 + n2)
                      + n4 * (n0 + n1 + n2 + n3);
        if (cnt > 0) {
            atomicAdd(&g_sum, s / (float)cnt);
            atomicAdd(&g_valid, 1);
        }
        __threadfence();
        const int prev = atomicAdd(&g_done, 1);
        if (prev == LL_B - 1) {
            const float gs = g_sum;
            const int   gv = g_valid;
            out[0] = (gv > 0) ? (gs / (float)gv) : 0.0f;
            g_sum   = 0.0f;
            g_valid = 0;
            g_done  = 0;
        }
    }
}

extern "C" void kernel_launch(void* const* d_in, const int* in_sizes, int n_in,
                              void* d_out, int out_size)
{
    const float* pred = (const float*)d_in[0];
    const float* rel  = (const float*)d_in[1];
    float* out = (float*)d_out;

    ll_main_kernel<<<LL_B / 2, 128>>>(pred, rel, out);
}